// round 5
// baseline (speedup 1.0000x reference)
#include <cuda_runtime.h>

// Problem constants
#define NB    32      // batch
#define NN    64      // objects
#define SSTR  260     // smem row stride (floats): even, 16B-aligned rows (260*4=1040? 1040%16=0 -> yes)

// Scratch (device globals: no allocation allowed)
__device__ float g_A[NB * NN * 256];   // x_i @ g1_w[0:65]
__device__ float g_C[NB * NN * 256];   // x_j @ g1_w[65:194] + g1_b
__device__ float g_xg[NB * 256];       // pooled sums

// ---------------- packed f32x2 helpers ----------------
__device__ __forceinline__ unsigned long long pack2(float lo, float hi) {
    unsigned long long r;
    asm("mov.b64 %0, {%1, %2};" : "=l"(r) : "f"(lo), "f"(hi));
    return r;
}
__device__ __forceinline__ void unpack2(unsigned long long v, float& lo, float& hi) {
    asm("mov.b64 {%0, %1}, %2;" : "=f"(lo), "=f"(hi) : "l"(v));
}
__device__ __forceinline__ unsigned long long fma2(unsigned long long a,
                                                   unsigned long long b,
                                                   unsigned long long c) {
    unsigned long long d;
    asm("fma.rn.f32x2 %0, %1, %2, %3;" : "=l"(d) : "l"(a), "l"(b), "l"(c));
    return d;
}

// ---------------- Phase 0: A/C precompute (g1 decomposition) ----------------
// A[b,i,o] = sum_{k<64} x_aux[b,i,k]*g1w[k,o] + i*g1w[64,o]
// C[b,j,o] = sum_{k<128} x_aux[b,j,k]*g1w[65+k,o] + j*g1w[193,o] + g1b[o]
__global__ void __launch_bounds__(256) precompute_AC(
    const float* __restrict__ x_aux,
    const float* __restrict__ g1w,
    const float* __restrict__ g1b)
{
    int bi = blockIdx.x;          // b*64 + i
    int i  = bi & 63;
    int o  = threadIdx.x;
    __shared__ float xs[128];
    const float* xr = x_aux + (size_t)bi * 128;
    if (o < 128) xs[o] = xr[o];
    __syncthreads();

    float fi = (float)i;
    float accA = fi * g1w[64 * 256 + o];
#pragma unroll 8
    for (int k = 0; k < 64; k++) accA = fmaf(xs[k], g1w[k * 256 + o], accA);
    g_A[bi * 256 + o] = accA;

    float accC = fmaf(fi, g1w[193 * 256 + o], g1b[o]);
#pragma unroll 8
    for (int k = 0; k < 128; k++) accC = fmaf(xs[k], g1w[(65 + k) * 256 + o], accC);
    g_C[bi * 256 + o] = accC;

    if (i == 0) g_xg[(bi >> 6) * 256 + o] = 0.f;   // zero the pooled accumulator
}

// ---------------- Fused 64x256 @ 256x256 layer (relu) ----------------
// Thread (tx 0..31, ty 0..7): rows ty*8+rr (rr<8), col pairs {2*tx+64*q, +1} (q<4).
__device__ __forceinline__ void mlp_layer(
    const float* __restrict__ in_s, float* __restrict__ out_s,
    float* __restrict__ Ws,
    const float* __restrict__ W, const float* __restrict__ bias,
    int tx, int ty, int tid)
{
    unsigned long long acc[8][4];
#pragma unroll
    for (int q = 0; q < 4; q++) {
        float2 bv = *(const float2*)(bias + 2 * tx + 64 * q);
        unsigned long long bb = pack2(bv.x, bv.y);
#pragma unroll
        for (int rr = 0; rr < 8; rr++) acc[rr][q] = bb;
    }

#pragma unroll 1
    for (int kt = 0; kt < 256; kt += 32) {
        __syncthreads();
        // stage W rows [kt, kt+32) : 8192 floats = 2048 float4, 8 per thread
        const float4* Wg = (const float4*)(W + kt * 256);
#pragma unroll
        for (int it = 0; it < 8; it++) {
            int v   = tid + 256 * it;     // float4 index within tile
            int row = v >> 6;             // 64 float4 per 256-float row
            int c4  = v & 63;
            *(float4*)(Ws + row * SSTR + c4 * 4) = Wg[v];
        }
        __syncthreads();

#pragma unroll 8
        for (int kk = 0; kk < 32; kk++) {
            int k = kt + kk;
            unsigned long long bv[4];
#pragma unroll
            for (int q = 0; q < 4; q++)
                bv[q] = *(const unsigned long long*)(Ws + kk * SSTR + 2 * tx + 64 * q);
#pragma unroll
            for (int rr = 0; rr < 8; rr++) {
                float a = in_s[(ty * 8 + rr) * SSTR + k];   // warp-broadcast
                unsigned long long a2 = pack2(a, a);
#pragma unroll
                for (int q = 0; q < 4; q++)
                    acc[rr][q] = fma2(a2, bv[q], acc[rr][q]);
            }
        }
    }

    // relu + write (no sync needed: out_s disjoint from in_s/Ws readers;
    // next layer's leading __syncthreads orders everything)
#pragma unroll
    for (int rr = 0; rr < 8; rr++) {
#pragma unroll
        for (int q = 0; q < 4; q++) {
            float lo, hi;
            unpack2(acc[rr][q], lo, hi);
            float2 v;
            v.x = fmaxf(lo, 0.f);
            v.y = fmaxf(hi, 0.f);
            *(float2*)(out_s + (ty * 8 + rr) * SSTR + 2 * tx + 64 * q) = v;
        }
    }
}

// ---------------- Phase 1: fused g2..g4 + pooling ----------------
// One CTA per (b, i): 64 pairs (all j), h1 = relu(A[b,i] + C[b,j]).
__global__ void __launch_bounds__(256) main_kernel(
    const float* __restrict__ g2w, const float* __restrict__ g2b,
    const float* __restrict__ g3w, const float* __restrict__ g3b,
    const float* __restrict__ g4w, const float* __restrict__ g4b)
{
    extern __shared__ float smem[];
    float* bufA = smem;                 // 64 x SSTR
    float* bufB = smem + 64 * SSTR;     // 64 x SSTR
    float* Ws   = smem + 128 * SSTR;    // 32 x SSTR

    int bi  = blockIdx.x;               // b*64 + i
    int b   = bi >> 6;
    int tid = threadIdx.x;
    int tx  = tid & 31;
    int ty  = tid >> 5;

    // h1 fill: bufA[j][o] = relu(A[b,i,o] + C[b,j,o])
    float a_o = g_A[bi * 256 + tid];
    const float* Cb = g_C + (size_t)b * NN * 256;
#pragma unroll 4
    for (int j = 0; j < 64; j++)
        bufA[j * SSTR + tid] = fmaxf(a_o + Cb[j * 256 + tid], 0.f);

    mlp_layer(bufA, bufB, Ws, g2w, g2b, tx, ty, tid);
    mlp_layer(bufB, bufA, Ws, g3w, g3b, tx, ty, tid);
    mlp_layer(bufA, bufB, Ws, g4w, g4b, tx, ty, tid);
    __syncthreads();

    // column-sum over the 64 pairs of this tile, accumulate into g_xg[b]
    float s = 0.f;
#pragma unroll 8
    for (int j = 0; j < 64; j++) s += bufB[j * SSTR + tid];
    atomicAdd(&g_xg[b * 256 + tid], s);
}

// ---------------- Phase 2: f-MLP (tiny: 32 rows) ----------------
__global__ void __launch_bounds__(256) f_mlp(
    const float* __restrict__ f1w, const float* __restrict__ f1b,
    const float* __restrict__ f2w, const float* __restrict__ f2b,
    const float* __restrict__ f3w, const float* __restrict__ f3b,
    float* __restrict__ out)
{
    int b = blockIdx.x;
    int o = threadIdx.x;
    __shared__ float xs[256];
    __shared__ float ys[256];

    xs[o] = g_xg[b * 256 + o];
    __syncthreads();

    float acc = f1b[o];
#pragma unroll 16
    for (int k = 0; k < 256; k++) acc = fmaf(xs[k], f1w[k * 256 + o], acc);
    ys[o] = fmaxf(acc, 0.f);
    __syncthreads();

    acc = f2b[o];
#pragma unroll 16
    for (int k = 0; k < 256; k++) acc = fmaf(ys[k], f2w[k * 256 + o], acc);
    xs[o] = fmaxf(acc, 0.f);
    __syncthreads();

    acc = f3b[o];
#pragma unroll 16
    for (int k = 0; k < 256; k++) acc = fmaf(xs[k], f3w[k * 256 + o], acc);
    out[b * 256 + o] = acc;
}

// ---------------- launch ----------------
extern "C" void kernel_launch(void* const* d_in, const int* in_sizes, int n_in,
                              void* d_out, int out_size)
{
    const float* x_aux = (const float*)d_in[0];
    const float* g1w   = (const float*)d_in[1];
    const float* g1b   = (const float*)d_in[2];
    const float* g2w   = (const float*)d_in[3];
    const float* g2b   = (const float*)d_in[4];
    const float* g3w   = (const float*)d_in[5];
    const float* g3b   = (const float*)d_in[6];
    const float* g4w   = (const float*)d_in[7];
    const float* g4b   = (const float*)d_in[8];
    const float* f1w   = (const float*)d_in[9];
    const float* f1b   = (const float*)d_in[10];
    const float* f2w   = (const float*)d_in[11];
    const float* f2b   = (const float*)d_in[12];
    const float* f3w   = (const float*)d_in[13];
    const float* f3b   = (const float*)d_in[14];
    float* out = (float*)d_out;

    const int smem_bytes = (128 * SSTR + 32 * SSTR) * 4;   // 166400 B
    cudaFuncSetAttribute(main_kernel, cudaFuncAttributeMaxDynamicSharedMemorySize, smem_bytes);

    precompute_AC<<<NB * NN, 256>>>(x_aux, g1w, g1b);
    main_kernel<<<NB * NN, 256, smem_bytes>>>(g2w, g2b, g3w, g3b, g4w, g4b);
    f_mlp<<<NB, 256>>>(f1w, f1b, f2w, f2b, f3w, f3b, out);
}

// round 8
// speedup vs baseline: 4.1917x; 4.1917x over previous
#include <cuda_runtime.h>
#include <cuda_bf16.h>

#define NB 32
#define NN 64

// ---------------- device scratch ----------------
__device__ float g_A[NB * NN * 256];
__device__ float g_C[NB * NN * 256];
__device__ float g_xg[NB * 256];
// 24 pieces of 32KB: p = L*8 + half*4 + kchunk ; layout [n=256][kchunk=64] bf16, XOR-swizzled
__device__ __align__(128) unsigned char g_Wp[24 * 32768];

// smem layout (bytes) for main kernel
#define A_OFF    0            // 4 k-chunks x (128 rows x 128B) = 65536
#define W_OFF    65536        // 2 slots x (hi 32KB + lo 32KB) = 131072
#define BIAS_OFF 196608       // 3 x 256 floats = 3072
#define SMEM_SZ  199680

// ---------------- PTX helpers (family-portable only) ----------------
__device__ __forceinline__ unsigned s2u(const void* p) {
    unsigned a;
    asm("{ .reg .u64 t; cvta.to.shared.u64 t, %1; cvt.u32.u64 %0, t; }" : "=r"(a) : "l"(p));
    return a;
}
__device__ __forceinline__ void ldsm_x4(unsigned addr, unsigned& r0, unsigned& r1,
                                        unsigned& r2, unsigned& r3) {
    asm volatile("ldmatrix.sync.aligned.m8n8.x4.shared.b16 {%0,%1,%2,%3}, [%4];"
                 : "=r"(r0), "=r"(r1), "=r"(r2), "=r"(r3) : "r"(addr));
}
__device__ __forceinline__ void ldsm_x2(unsigned addr, unsigned& r0, unsigned& r1) {
    asm volatile("ldmatrix.sync.aligned.m8n8.x2.shared.b16 {%0,%1}, [%2];"
                 : "=r"(r0), "=r"(r1) : "r"(addr));
}
__device__ __forceinline__ void mma_bf16(float* c, const unsigned* a, unsigned b0, unsigned b1) {
    asm volatile("mma.sync.aligned.m16n8k16.row.col.f32.bf16.bf16.f32 "
                 "{%0,%1,%2,%3},{%4,%5,%6,%7},{%8,%9},{%0,%1,%2,%3};"
                 : "+f"(c[0]), "+f"(c[1]), "+f"(c[2]), "+f"(c[3])
                 : "r"(a[0]), "r"(a[1]), "r"(a[2]), "r"(a[3]), "r"(b0), "r"(b1));
}
__device__ __forceinline__ void cpasync16(unsigned s, const void* g) {
    asm volatile("cp.async.cg.shared.global [%0], [%1], 16;" :: "r"(s), "l"(g));
}
#define CP_COMMIT() asm volatile("cp.async.commit_group;" ::: "memory")
#define CP_WAIT1()  asm volatile("cp.async.wait_group 1;" ::: "memory")

__device__ __forceinline__ unsigned cvt_bf2(float hi, float lo) {
    unsigned r;
    asm("cvt.rn.bf16x2.f32 %0, %1, %2;" : "=r"(r) : "f"(hi), "f"(lo));   // [31:16]=hi,[15:0]=lo
    return r;
}

// ---------------- prep: weights -> bf16 hi/lo pieces [n][k64], swizzled ----------------
__global__ void __launch_bounds__(256) prep_w(
    const float* __restrict__ g2w, const float* __restrict__ g3w, const float* __restrict__ g4w)
{
    int p = blockIdx.x;                       // p = L*8 + half*4 + kc
    int L = p >> 3, h = (p >> 2) & 1, kc = p & 3;
    const float* W = (L == 0) ? g2w : (L == 1) ? g3w : g4w;
    int n = threadIdx.x;
    unsigned char* dst = g_Wp + (size_t)p * 32768;
#pragma unroll 4
    for (int k2 = 0; k2 < 32; ++k2) {
        int k = 2 * k2, kg = kc * 64 + k;
        float w0 = W[kg * 256 + n], w1 = W[(kg + 1) * 256 + n];
        unsigned pk;
        if (h == 0) {
            pk = cvt_bf2(w1, w0);
        } else {
            float r0 = w0 - __bfloat162float(__float2bfloat16(w0));
            float r1 = w1 - __bfloat162float(__float2bfloat16(w1));
            pk = cvt_bf2(r1, r0);
        }
        unsigned off = (unsigned)n * 128 + ((((unsigned)k >> 3) ^ ((unsigned)n & 7)) << 4)
                     + ((unsigned)k & 7) * 2;
        *(unsigned*)(dst + off) = pk;
    }
}

// ---------------- precompute A/C (g1 decomposition), 8 i's per block ----------------
__global__ void __launch_bounds__(256) precompute_AC(
    const float* __restrict__ x_aux, const float* __restrict__ g1w, const float* __restrict__ g1b)
{
    int blk = blockIdx.x;           // 256 blocks: b = blk>>3, ig = blk&7
    int b = blk >> 3, ig = blk & 7;
    int o = threadIdx.x;
    __shared__ float xs[8][128];
#pragma unroll
    for (int it = 0; it < 4; ++it) {
        int v = o + 256 * it, r = v >> 7, k = v & 127;
        xs[r][k] = x_aux[(size_t)(b * 64 + ig * 8 + r) * 128 + k];
    }
    __syncthreads();

    float w64 = g1w[64 * 256 + o], w193 = g1w[193 * 256 + o], bb = g1b[o];
    float accA[8], accC[8];
#pragma unroll
    for (int r = 0; r < 8; ++r) {
        float fi = (float)(ig * 8 + r);
        accA[r] = fi * w64;
        accC[r] = fmaf(fi, w193, bb);
    }
#pragma unroll 4
    for (int k = 0; k < 64; ++k) {
        float w = g1w[k * 256 + o];
#pragma unroll
        for (int r = 0; r < 8; ++r) accA[r] = fmaf(xs[r][k], w, accA[r]);
    }
#pragma unroll 4
    for (int k = 0; k < 128; ++k) {
        float w = g1w[(65 + k) * 256 + o];
#pragma unroll
        for (int r = 0; r < 8; ++r) accC[r] = fmaf(xs[r][k], w, accC[r]);
    }
#pragma unroll
    for (int r = 0; r < 8; ++r) {
        int biq = b * 64 + ig * 8 + r;
        g_A[biq * 256 + o] = accA[r];
        g_C[biq * 256 + o] = accC[r];
    }
    if (ig == 0) g_xg[b * 256 + o] = 0.f;
}

// ---------------- main: fused g2..g4 on mma.sync + pooling ----------------
__global__ void __launch_bounds__(256, 1) main_kernel(
    const float* __restrict__ g2b, const float* __restrict__ g3b, const float* __restrict__ g4b)
{
    extern __shared__ char smem[];
    unsigned sb = s2u(smem);
    int tid = threadIdx.x, l = tid & 31, wid = tid >> 5;
    int wm = wid & 1, wn = wid >> 1;                    // 2(M) x 4(N) warp grid
    int bi = blockIdx.x;                                // 1024 CTAs
    int b = bi >> 5, i0 = (bi & 31) * 2;

    float* bias_s = (float*)(smem + BIAS_OFF);
    bias_s[tid] = g2b[tid];
    bias_s[256 + tid] = g3b[tid];
    bias_s[512 + tid] = g4b[tid];

    // prologue: async-load weight steps 0 and 1 (each = hi+lo pieces of one k-chunk)
#pragma unroll 1
    for (int s = 0; s < 2; ++s) {
        int L = 0, c = s;
        const unsigned char* hi = g_Wp + (size_t)(L * 8 + c) * 32768;
        const unsigned char* lo = g_Wp + (size_t)(L * 8 + 4 + c) * 32768;
        unsigned dst = sb + W_OFF + s * 65536;
#pragma unroll
        for (int i = 0; i < 8; ++i) {
            int off = (tid + 256 * i) * 16;
            cpasync16(dst + off, hi + off);
        }
#pragma unroll
        for (int i = 0; i < 8; ++i) {
            int off = (tid + 256 * i) * 16;
            cpasync16(dst + 32768 + off, lo + off);
        }
        CP_COMMIT();
    }

    // ---- h1 fill: A chunks <- relu(gA[b,i] + gC[b,j]) as bf16, swizzled ----
    {
        int cp = tid & 127, jh = tid >> 7;
        int c0 = 2 * cp;
        float2 av0 = *(const float2*)(g_A + (size_t)(b * 64 + i0) * 256 + c0);
        float2 av1 = *(const float2*)(g_A + (size_t)(b * 64 + i0 + 1) * 256 + c0);
        const float* Cb = g_C + (size_t)(b * 64) * 256;
        unsigned cbase = (unsigned)(c0 >> 6) * 16384;
        unsigned kcol = (unsigned)((c0 & 63) >> 3);
        unsigned kbyt = (unsigned)(c0 & 7) * 2;
#pragma unroll 2
        for (int jj = 0; jj < 32; ++jj) {
            int j = jh * 32 + jj;
            float2 cv = *(const float2*)(Cb + (size_t)j * 256 + c0);
#pragma unroll
            for (int ii = 0; ii < 2; ++ii) {
                int m = ii * 64 + j;
                float ax = ii ? av1.x : av0.x, ay = ii ? av1.y : av0.y;
                float v0 = fmaxf(ax + cv.x, 0.f);
                float v1 = fmaxf(ay + cv.y, 0.f);
                unsigned off = cbase + (unsigned)m * 128
                             + ((kcol ^ ((unsigned)m & 7)) << 4) + kbyt;
                *(unsigned*)(smem + off) = cvt_bf2(v1, v0);
            }
        }
    }
    __syncthreads();

    // lane-constant address components
    unsigned arow = (unsigned)(wm * 64 + (l & 15));
    unsigned abase = sb + arow * 128;           // A_OFF = 0
    unsigned asw = (unsigned)(l & 7);
    unsigned ahb = (unsigned)(l >> 4);
    int lb = l & 15;
    unsigned bbase = sb + W_OFF + (unsigned)(wn * 64 + (lb & 7)) * 128;
    unsigned bsw = (unsigned)(lb & 7);
    unsigned bhb = (unsigned)(lb >> 3);

    float acc[4][8][4];
    unsigned esw = (unsigned)(l >> 2);          // row&7 in epilogue
    int cl = l & 3;

#pragma unroll 1
    for (int t = 0; t < 12; ++t) {
        CP_WAIT1();
        __syncthreads();
        int slot = t & 1, c = t & 3;

        if (c == 0) {
#pragma unroll
            for (int mt = 0; mt < 4; ++mt)
#pragma unroll
                for (int nt = 0; nt < 8; ++nt)
#pragma unroll
                    for (int e = 0; e < 4; ++e) acc[mt][nt][e] = 0.f;
        }

        unsigned acb = abase + (unsigned)c * 16384;
        unsigned bsl = bbase + (unsigned)slot * 65536;
#pragma unroll
        for (int ks = 0; ks < 4; ++ks) {
            unsigned a[4][4];
            unsigned kxa = (((unsigned)(ks * 2) + ahb) ^ asw) << 4;
#pragma unroll
            for (int mt = 0; mt < 4; ++mt)
                ldsm_x4(acb + mt * 2048 + kxa, a[mt][0], a[mt][1], a[mt][2], a[mt][3]);
            unsigned kxb = (((unsigned)(ks * 2) + bhb) ^ bsw) << 4;
#pragma unroll
            for (int h = 0; h < 2; ++h) {
                unsigned bh = bsl + h * 32768 + kxb;
#pragma unroll
                for (int nt = 0; nt < 8; ++nt) {
                    unsigned b0, b1;
                    ldsm_x2(bh + nt * 1024, b0, b1);
#pragma unroll
                    for (int mt = 0; mt < 4; ++mt)
                        mma_bf16(acc[mt][nt], a[mt], b0, b1);
                }
            }
        }
        __syncthreads();   // all reads of W slot + A done

        // prefetch step t+2 into the slot just freed
        if (t + 2 < 12) {
            int st = t + 2, L2i = st >> 2, c2 = st & 3;
            const unsigned char* hi = g_Wp + (size_t)(L2i * 8 + c2) * 32768;
            const unsigned char* lo = g_Wp + (size_t)(L2i * 8 + 4 + c2) * 32768;
            unsigned dst = sb + W_OFF + slot * 65536;
#pragma unroll
            for (int i = 0; i < 8; ++i) {
                int off = (tid + 256 * i) * 16;
                cpasync16(dst + off, hi + off);
            }
#pragma unroll
            for (int i = 0; i < 8; ++i) {
                int off = (tid + 256 * i) * 16;
                cpasync16(dst + 32768 + off, lo + off);
            }
        }
        CP_COMMIT();

        if (c == 3) {
            int L = t >> 2;
            if (L < 2) {
                // bias+relu, write back as next layer's A (bf16, swizzled)
                int r0 = wm * 64 + (l >> 2);
#pragma unroll
                for (int nt = 0; nt < 8; ++nt) {
                    float b0 = bias_s[L * 256 + wn * 64 + nt * 8 + 2 * cl];
                    float b1 = bias_s[L * 256 + wn * 64 + nt * 8 + 2 * cl + 1];
#pragma unroll
                    for (int mt = 0; mt < 4; ++mt) {
                        int ra = r0 + mt * 16, rb = ra + 8;
                        unsigned pa = cvt_bf2(fmaxf(acc[mt][nt][1] + b1, 0.f),
                                              fmaxf(acc[mt][nt][0] + b0, 0.f));
                        unsigned pb = cvt_bf2(fmaxf(acc[mt][nt][3] + b1, 0.f),
                                              fmaxf(acc[mt][nt][2] + b0, 0.f));
                        unsigned swc = ((unsigned)nt ^ esw) << 4;
                        *(unsigned*)(smem + wn * 16384 + ra * 128 + swc + 4 * cl) = pa;
                        *(unsigned*)(smem + wn * 16384 + rb * 128 + swc + 4 * cl) = pb;
                    }
                }
            } else {
                // g4: bias+relu, row-sum, atomic pool
#pragma unroll
                for (int nt = 0; nt < 8; ++nt) {
                    float b0 = bias_s[512 + wn * 64 + nt * 8 + 2 * cl];
                    float b1 = bias_s[512 + wn * 64 + nt * 8 + 2 * cl + 1];
                    float s0 = 0.f, s1 = 0.f;
#pragma unroll
                    for (int mt = 0; mt < 4; ++mt) {
                        s0 += fmaxf(acc[mt][nt][0] + b0, 0.f) + fmaxf(acc[mt][nt][2] + b0, 0.f);
                        s1 += fmaxf(acc[mt][nt][1] + b1, 0.f) + fmaxf(acc[mt][nt][3] + b1, 0.f);
                    }
                    s0 += __shfl_xor_sync(0xFFFFFFFFu, s0, 4);
                    s0 += __shfl_xor_sync(0xFFFFFFFFu, s0, 8);
                    s0 += __shfl_xor_sync(0xFFFFFFFFu, s0, 16);
                    s1 += __shfl_xor_sync(0xFFFFFFFFu, s1, 4);
                    s1 += __shfl_xor_sync(0xFFFFFFFFu, s1, 8);
                    s1 += __shfl_xor_sync(0xFFFFFFFFu, s1, 16);
                    if (l < 4) {
                        atomicAdd(&g_xg[b * 256 + wn * 64 + nt * 8 + 2 * l], s0);
                        atomicAdd(&g_xg[b * 256 + wn * 64 + nt * 8 + 2 * l + 1], s1);
                    }
                }
            }
            __syncthreads();
        }
    }
}

// ---------------- f-MLP ----------------
__global__ void __launch_bounds__(256) f_mlp(
    const float* __restrict__ f1w, const float* __restrict__ f1b,
    const float* __restrict__ f2w, const float* __restrict__ f2b,
    const float* __restrict__ f3w, const float* __restrict__ f3b,
    float* __restrict__ out)
{
    int b = blockIdx.x;
    int o = threadIdx.x;
    __shared__ float xs[256];
    __shared__ float ys[256];

    xs[o] = g_xg[b * 256 + o];
    __syncthreads();

    float acc = f1b[o];
#pragma unroll 16
    for (int k = 0; k < 256; k++) acc = fmaf(xs[k], f1w[k * 256 + o], acc);
    ys[o] = fmaxf(acc, 0.f);
    __syncthreads();

    acc = f2b[o];
#pragma unroll 16
    for (int k = 0; k < 256; k++) acc = fmaf(ys[k], f2w[k * 256 + o], acc);
    xs[o] = fmaxf(acc, 0.f);
    __syncthreads();

    acc = f3b[o];
#pragma unroll 16
    for (int k = 0; k < 256; k++) acc = fmaf(xs[k], f3w[k * 256 + o], acc);
    out[b * 256 + o] = acc;
}

// ---------------- launch ----------------
extern "C" void kernel_launch(void* const* d_in, const int* in_sizes, int n_in,
                              void* d_out, int out_size)
{
    const float* x_aux = (const float*)d_in[0];
    const float* g1w   = (const float*)d_in[1];
    const float* g1b   = (const float*)d_in[2];
    const float* g2w   = (const float*)d_in[3];
    const float* g2b   = (const float*)d_in[4];
    const float* g3w   = (const float*)d_in[5];
    const float* g3b   = (const float*)d_in[6];
    const float* g4w   = (const float*)d_in[7];
    const float* g4b   = (const float*)d_in[8];
    const float* f1w   = (const float*)d_in[9];
    const float* f1b   = (const float*)d_in[10];
    const float* f2w   = (const float*)d_in[11];
    const float* f2b   = (const float*)d_in[12];
    const float* f3w   = (const float*)d_in[13];
    const float* f3b   = (const float*)d_in[14];
    float* out = (float*)d_out;

    cudaFuncSetAttribute(main_kernel, cudaFuncAttributeMaxDynamicSharedMemorySize, SMEM_SZ);

    prep_w<<<24, 256>>>(g2w, g3w, g4w);
    precompute_AC<<<256, 256>>>(x_aux, g1w, g1b);
    main_kernel<<<1024, 256, SMEM_SZ>>>(g2b, g3b, g4b);
    f_mlp<<<NB, 256>>>(f1w, f1b, f2w, f2b, f3w, f3b, out);
}

// round 9
// speedup vs baseline: 6.5612x; 1.5653x over previous
#include <cuda_runtime.h>
#include <cuda_fp16.h>

#define NB 32
#define NN 64

// ---------------- device scratch ----------------
__device__ float g_A[NB * NN * 256];
__device__ float g_C[NB * NN * 256];
__device__ float g_xg[NB * 256];
__device__ float g_f1[NB * 256];
__device__ float g_f2[NB * 256];
// 12 pieces of 32KB: p = L*4 + kchunk ; layout [n=256][kchunk=64] f16, XOR-swizzled
__device__ __align__(128) unsigned char g_Wp[12 * 32768];

// smem layout (bytes) for main kernel
#define A_OFF    0            // 4 k-chunks x (128 rows x 128B) = 65536
#define W_OFF    65536        // 2 slots x 32KB = 65536
#define BIAS_OFF 131072       // 3 x 256 floats = 3072
#define SMEM_SZ  134144

// ---------------- PTX helpers (family-portable only) ----------------
__device__ __forceinline__ unsigned s2u(const void* p) {
    unsigned a;
    asm("{ .reg .u64 t; cvta.to.shared.u64 t, %1; cvt.u32.u64 %0, t; }" : "=r"(a) : "l"(p));
    return a;
}
__device__ __forceinline__ void ldsm_x4(unsigned addr, unsigned& r0, unsigned& r1,
                                        unsigned& r2, unsigned& r3) {
    asm volatile("ldmatrix.sync.aligned.m8n8.x4.shared.b16 {%0,%1,%2,%3}, [%4];"
                 : "=r"(r0), "=r"(r1), "=r"(r2), "=r"(r3) : "r"(addr));
}
__device__ __forceinline__ void mma_f16(float* c, const unsigned* a, unsigned b0, unsigned b1) {
    asm volatile("mma.sync.aligned.m16n8k16.row.col.f32.f16.f16.f32 "
                 "{%0,%1,%2,%3},{%4,%5,%6,%7},{%8,%9},{%0,%1,%2,%3};"
                 : "+f"(c[0]), "+f"(c[1]), "+f"(c[2]), "+f"(c[3])
                 : "r"(a[0]), "r"(a[1]), "r"(a[2]), "r"(a[3]), "r"(b0), "r"(b1));
}
__device__ __forceinline__ void cpasync16(unsigned s, const void* g) {
    asm volatile("cp.async.cg.shared.global [%0], [%1], 16;" :: "r"(s), "l"(g));
}
#define CP_COMMIT() asm volatile("cp.async.commit_group;" ::: "memory")
#define CP_WAIT1()  asm volatile("cp.async.wait_group 1;" ::: "memory")

__device__ __forceinline__ unsigned cvt_h2(float hi, float lo) {
    unsigned r;
    asm("cvt.rn.f16x2.f32 %0, %1, %2;" : "=r"(r) : "f"(hi), "f"(lo));   // [31:16]=hi,[15:0]=lo
    return r;
}

// ---------------- merged prep: precompute A/C  +  weight f16 pieces ----------------
__global__ void __launch_bounds__(256) prep_all(
    const float* __restrict__ x_aux, const float* __restrict__ g1w, const float* __restrict__ g1b,
    const float* __restrict__ g2w, const float* __restrict__ g3w, const float* __restrict__ g4w)
{
    int blk = blockIdx.x;
    if (blk >= 256) {
        // ---- weight piece p = L*4 + kc : [n=256][k=64] f16, XOR swizzle ----
        int p = blk - 256;
        int L = p >> 2, kc = p & 3;
        const float* W = (L == 0) ? g2w : (L == 1) ? g3w : g4w;
        int n = threadIdx.x;
        unsigned char* dst = g_Wp + (size_t)p * 32768;
#pragma unroll 4
        for (int k2 = 0; k2 < 32; ++k2) {
            int k = 2 * k2, kg = kc * 64 + k;
            float w0 = W[kg * 256 + n], w1 = W[(kg + 1) * 256 + n];
            unsigned off = (unsigned)n * 128 + ((((unsigned)k >> 3) ^ ((unsigned)n & 7)) << 4)
                         + ((unsigned)k & 7) * 2;
            *(unsigned*)(dst + off) = cvt_h2(w1, w0);
        }
        return;
    }
    // ---- A/C precompute (g1 decomposition), 8 i's per block ----
    int b = blk >> 3, ig = blk & 7;
    int o = threadIdx.x;
    __shared__ float xs[8][128];
#pragma unroll
    for (int it = 0; it < 4; ++it) {
        int v = o + 256 * it, r = v >> 7, k = v & 127;
        xs[r][k] = x_aux[(size_t)(b * 64 + ig * 8 + r) * 128 + k];
    }
    __syncthreads();

    float w64 = g1w[64 * 256 + o], w193 = g1w[193 * 256 + o], bb = g1b[o];
    float accA[8], accC[8];
#pragma unroll
    for (int r = 0; r < 8; ++r) {
        float fi = (float)(ig * 8 + r);
        accA[r] = fi * w64;
        accC[r] = fmaf(fi, w193, bb);
    }
#pragma unroll 4
    for (int k = 0; k < 64; ++k) {
        float w = g1w[k * 256 + o];
#pragma unroll
        for (int r = 0; r < 8; ++r) accA[r] = fmaf(xs[r][k], w, accA[r]);
    }
#pragma unroll 4
    for (int k = 0; k < 128; ++k) {
        float w = g1w[(65 + k) * 256 + o];
#pragma unroll
        for (int r = 0; r < 8; ++r) accC[r] = fmaf(xs[r][k], w, accC[r]);
    }
#pragma unroll
    for (int r = 0; r < 8; ++r) {
        int biq = b * 64 + ig * 8 + r;
        g_A[biq * 256 + o] = accA[r];
        g_C[biq * 256 + o] = accC[r];
    }
    if (ig == 0) g_xg[b * 256 + o] = 0.f;
}

// ---------------- main: fused g2..g4 on mma.sync f16 + pooling ----------------
__global__ void __launch_bounds__(256, 1) main_kernel(
    const float* __restrict__ g2b, const float* __restrict__ g3b, const float* __restrict__ g4b)
{
    extern __shared__ char smem[];
    unsigned sb = s2u(smem);
    int tid = threadIdx.x, l = tid & 31, wid = tid >> 5;
    int wm = wid & 1, wn = wid >> 1;                    // 2(M) x 4(N) warp grid
    int bi = blockIdx.x;                                // 1024 CTAs
    int b = bi >> 5, i0 = (bi & 31) * 2;

    float* bias_s = (float*)(smem + BIAS_OFF);
    bias_s[tid] = g2b[tid];
    bias_s[256 + tid] = g3b[tid];
    bias_s[512 + tid] = g4b[tid];

    // prologue: async-load weight pieces 0 and 1 (32KB each)
#pragma unroll
    for (int s = 0; s < 2; ++s) {
        const unsigned char* src = g_Wp + (size_t)s * 32768;
        unsigned dst = sb + W_OFF + s * 32768;
#pragma unroll
        for (int i = 0; i < 8; ++i) {
            int off = (tid + 256 * i) * 16;
            cpasync16(dst + off, src + off);
        }
        CP_COMMIT();
    }

    // ---- h1 fill: A chunks <- relu(gA[b,i] + gC[b,j]) as f16, swizzled ----
    {
        int cp = tid & 127, jh = tid >> 7;
        int c0 = 2 * cp;
        float2 av0 = *(const float2*)(g_A + (size_t)(b * 64 + i0) * 256 + c0);
        float2 av1 = *(const float2*)(g_A + (size_t)(b * 64 + i0 + 1) * 256 + c0);
        const float* Cb = g_C + (size_t)(b * 64) * 256;
        unsigned cbase = (unsigned)(c0 >> 6) * 16384;
        unsigned kcol = (unsigned)((c0 & 63) >> 3);
        unsigned kbyt = (unsigned)(c0 & 7) * 2;
#pragma unroll 2
        for (int jj = 0; jj < 32; ++jj) {
            int j = jh * 32 + jj;
            float2 cv = *(const float2*)(Cb + (size_t)j * 256 + c0);
#pragma unroll
            for (int ii = 0; ii < 2; ++ii) {
                int m = ii * 64 + j;
                float ax = ii ? av1.x : av0.x, ay = ii ? av1.y : av0.y;
                float v0 = fmaxf(ax + cv.x, 0.f);
                float v1 = fmaxf(ay + cv.y, 0.f);
                unsigned off = cbase + (unsigned)m * 128
                             + ((kcol ^ ((unsigned)m & 7)) << 4) + kbyt;
                *(unsigned*)(smem + off) = cvt_h2(v1, v0);
            }
        }
    }
    __syncthreads();

    // lane-constant address components
    unsigned arow = (unsigned)(wm * 64 + (l & 15));
    unsigned abase = sb + arow * 128;           // A_OFF = 0
    unsigned asw = (unsigned)(l & 7);
    unsigned ahb = (unsigned)(l >> 4);
    // B ldsm_x4 lane mapping: row=(l&7), k-half=(l>>3)&1, nt-offset=(l>>4)
    unsigned bbase = sb + W_OFF + (unsigned)((wn * 64 + (l >> 4) * 8 + (l & 7)) * 128);
    unsigned bsw = (unsigned)(l & 7);
    unsigned bhb = (unsigned)((l >> 3) & 1);

    float acc[4][8][4];
    unsigned esw = (unsigned)(l >> 2);          // row&7 in epilogue
    int cl = l & 3;

#pragma unroll 1
    for (int t = 0; t < 12; ++t) {
        CP_WAIT1();
        __syncthreads();
        int slot = t & 1, c = t & 3;

        if (c == 0) {
#pragma unroll
            for (int mt = 0; mt < 4; ++mt)
#pragma unroll
                for (int nt = 0; nt < 8; ++nt)
#pragma unroll
                    for (int e = 0; e < 4; ++e) acc[mt][nt][e] = 0.f;
        }

        unsigned acb = abase + (unsigned)c * 16384;
        unsigned bsl = bbase + (unsigned)slot * 32768;
#pragma unroll
        for (int ks = 0; ks < 4; ++ks) {
            unsigned a[4][4];
            unsigned kxa = (((unsigned)(ks * 2) + ahb) ^ asw) << 4;
#pragma unroll
            for (int mt = 0; mt < 4; ++mt)
                ldsm_x4(acb + mt * 2048 + kxa, a[mt][0], a[mt][1], a[mt][2], a[mt][3]);
            unsigned kxb = (((unsigned)(ks * 2) + bhb) ^ bsw) << 4;
#pragma unroll
            for (int np = 0; np < 4; ++np) {
                unsigned b0, b1, b2, b3;
                ldsm_x4(bsl + np * 2048 + kxb, b0, b1, b2, b3);
#pragma unroll
                for (int mt = 0; mt < 4; ++mt) {
                    mma_f16(acc[mt][2 * np], a[mt], b0, b1);
                    mma_f16(acc[mt][2 * np + 1], a[mt], b2, b3);
                }
            }
        }
        __syncthreads();   // all reads of W slot + A done

        // prefetch step t+2 into the slot just freed
        if (t + 2 < 12) {
            const unsigned char* src = g_Wp + (size_t)(t + 2) * 32768;
            unsigned dst = sb + W_OFF + slot * 32768;
#pragma unroll
            for (int i = 0; i < 8; ++i) {
                int off = (tid + 256 * i) * 16;
                cpasync16(dst + off, src + off);
            }
        }
        CP_COMMIT();

        if (c == 3) {
            int L = t >> 2;
            if (L < 2) {
                // bias+relu, write back as next layer's A (f16, swizzled)
                int r0 = wm * 64 + (l >> 2);
#pragma unroll
                for (int nt = 0; nt < 8; ++nt) {
                    float b0 = bias_s[L * 256 + wn * 64 + nt * 8 + 2 * cl];
                    float b1 = bias_s[L * 256 + wn * 64 + nt * 8 + 2 * cl + 1];
#pragma unroll
                    for (int mt = 0; mt < 4; ++mt) {
                        int ra = r0 + mt * 16, rb = ra + 8;
                        unsigned pa = cvt_h2(fmaxf(acc[mt][nt][1] + b1, 0.f),
                                             fmaxf(acc[mt][nt][0] + b0, 0.f));
                        unsigned pb = cvt_h2(fmaxf(acc[mt][nt][3] + b1, 0.f),
                                             fmaxf(acc[mt][nt][2] + b0, 0.f));
                        unsigned swc = ((unsigned)nt ^ esw) << 4;
                        *(unsigned*)(smem + wn * 16384 + ra * 128 + swc + 4 * cl) = pa;
                        *(unsigned*)(smem + wn * 16384 + rb * 128 + swc + 4 * cl) = pb;
                    }
                }
            } else {
                // g4: bias+relu, row-sum, atomic pool
#pragma unroll
                for (int nt = 0; nt < 8; ++nt) {
                    float b0 = bias_s[512 + wn * 64 + nt * 8 + 2 * cl];
                    float b1 = bias_s[512 + wn * 64 + nt * 8 + 2 * cl + 1];
                    float s0 = 0.f, s1 = 0.f;
#pragma unroll
                    for (int mt = 0; mt < 4; ++mt) {
                        s0 += fmaxf(acc[mt][nt][0] + b0, 0.f) + fmaxf(acc[mt][nt][2] + b0, 0.f);
                        s1 += fmaxf(acc[mt][nt][1] + b1, 0.f) + fmaxf(acc[mt][nt][3] + b1, 0.f);
                    }
                    s0 += __shfl_xor_sync(0xFFFFFFFFu, s0, 4);
                    s0 += __shfl_xor_sync(0xFFFFFFFFu, s0, 8);
                    s0 += __shfl_xor_sync(0xFFFFFFFFu, s0, 16);
                    s1 += __shfl_xor_sync(0xFFFFFFFFu, s1, 4);
                    s1 += __shfl_xor_sync(0xFFFFFFFFu, s1, 8);
                    s1 += __shfl_xor_sync(0xFFFFFFFFu, s1, 16);
                    if (l < 4) {
                        atomicAdd(&g_xg[b * 256 + wn * 64 + nt * 8 + 2 * l], s0);
                        atomicAdd(&g_xg[b * 256 + wn * 64 + nt * 8 + 2 * l + 1], s1);
                    }
                }
            }
            __syncthreads();
        }
    }
}

// ---------------- f-MLP: one layer per launch, k-split across warps ----------------
// grid = 256: b = blk>>3, og = blk&7. thread: o = og*32 + (tid&31), kpart = tid>>5.
__global__ void __launch_bounds__(256) f_layer(
    const float* __restrict__ in, const float* __restrict__ W, const float* __restrict__ bias,
    float* __restrict__ out, int do_relu)
{
    int blk = blockIdx.x;
    int b = blk >> 3, og = blk & 7;
    int tid = threadIdx.x;
    int ol = tid & 31, kp = tid >> 5;
    int o = og * 32 + ol;

    __shared__ float xs[256];
    __shared__ float red[256];
    xs[tid] = in[b * 256 + tid];
    __syncthreads();

    float acc = 0.f;
#pragma unroll
    for (int kk = 0; kk < 32; ++kk) {
        int k = kp * 32 + kk;
        acc = fmaf(xs[k], W[k * 256 + o], acc);
    }
    red[tid] = acc;
    __syncthreads();

    if (tid < 32) {
        float s = red[tid];
#pragma unroll
        for (int j = 1; j < 8; ++j) s += red[tid + 32 * j];
        s += bias[og * 32 + tid];
        if (do_relu) s = fmaxf(s, 0.f);
        out[b * 256 + og * 32 + tid] = s;
    }
}

// ---------------- launch ----------------
extern "C" void kernel_launch(void* const* d_in, const int* in_sizes, int n_in,
                              void* d_out, int out_size)
{
    const float* x_aux = (const float*)d_in[0];
    const float* g1w   = (const float*)d_in[1];
    const float* g1b   = (const float*)d_in[2];
    const float* g2w   = (const float*)d_in[3];
    const float* g2b   = (const float*)d_in[4];
    const float* g3w   = (const float*)d_in[5];
    const float* g3b   = (const float*)d_in[6];
    const float* g4w   = (const float*)d_in[7];
    const float* g4b   = (const float*)d_in[8];
    const float* f1w   = (const float*)d_in[9];
    const float* f1b   = (const float*)d_in[10];
    const float* f2w   = (const float*)d_in[11];
    const float* f2b   = (const float*)d_in[12];
    const float* f3w   = (const float*)d_in[13];
    const float* f3b   = (const float*)d_in[14];
    float* out = (float*)d_out;

    float* xg;  cudaGetSymbolAddress((void**)&xg,  g_xg);
    float* xf1; cudaGetSymbolAddress((void**)&xf1, g_f1);
    float* xf2; cudaGetSymbolAddress((void**)&xf2, g_f2);

    cudaFuncSetAttribute(main_kernel, cudaFuncAttributeMaxDynamicSharedMemorySize, SMEM_SZ);

    prep_all<<<268, 256>>>(x_aux, g1w, g1b, g2w, g3w, g4w);
    main_kernel<<<1024, 256, SMEM_SZ>>>(g2b, g3b, g4b);
    f_layer<<<256, 256>>>(xg,  f1w, f1b, xf1, 1);
    f_layer<<<256, 256>>>(xf1, f2w, f2b, xf2, 1);
    f_layer<<<256, 256>>>(xf2, f3w, f3b, out, 0);
}

// round 10
// speedup vs baseline: 6.6974x; 1.0208x over previous
#include <cuda_runtime.h>
#include <cuda_fp16.h>

#define NB 32
#define NN 64

// ---------------- device scratch ----------------
__device__ float g_A[NB * NN * 256];
__device__ float g_C[NB * NN * 256];
__device__ float g_xg[NB * 256];
// 12 pieces of 32KB: p = L*4 + kchunk ; layout [n=256][kchunk=64] f16, XOR-swizzled
__device__ __align__(128) unsigned char g_Wp[12 * 32768];

// smem layout (bytes) for main kernel
#define A_OFF    0            // 4 k-chunks x (128 rows x 128B) = 65536
#define W_OFF    65536        // 3 slots x 32KB = 98304
#define BIAS_OFF 163840       // 3 x 256 floats = 3072
#define SMEM_SZ  166912

// ---------------- PTX helpers (family-portable only) ----------------
__device__ __forceinline__ unsigned s2u(const void* p) {
    unsigned a;
    asm("{ .reg .u64 t; cvta.to.shared.u64 t, %1; cvt.u32.u64 %0, t; }" : "=r"(a) : "l"(p));
    return a;
}
__device__ __forceinline__ void ldsm_x4(unsigned addr, unsigned& r0, unsigned& r1,
                                        unsigned& r2, unsigned& r3) {
    asm volatile("ldmatrix.sync.aligned.m8n8.x4.shared.b16 {%0,%1,%2,%3}, [%4];"
                 : "=r"(r0), "=r"(r1), "=r"(r2), "=r"(r3) : "r"(addr));
}
__device__ __forceinline__ void mma_f16(float* c, const unsigned* a, unsigned b0, unsigned b1) {
    asm volatile("mma.sync.aligned.m16n8k16.row.col.f32.f16.f16.f32 "
                 "{%0,%1,%2,%3},{%4,%5,%6,%7},{%8,%9},{%0,%1,%2,%3};"
                 : "+f"(c[0]), "+f"(c[1]), "+f"(c[2]), "+f"(c[3])
                 : "r"(a[0]), "r"(a[1]), "r"(a[2]), "r"(a[3]), "r"(b0), "r"(b1));
}
__device__ __forceinline__ void cpasync16(unsigned s, const void* g) {
    asm volatile("cp.async.cg.shared.global [%0], [%1], 16;" :: "r"(s), "l"(g));
}
#define CP_COMMIT() asm volatile("cp.async.commit_group;" ::: "memory")
#define CP_WAIT1()  asm volatile("cp.async.wait_group 1;" ::: "memory")

__device__ __forceinline__ unsigned cvt_h2(float hi, float lo) {
    unsigned r;
    asm("cvt.rn.f16x2.f32 %0, %1, %2;" : "=r"(r) : "f"(hi), "f"(lo));   // [31:16]=hi,[15:0]=lo
    return r;
}

// ---------------- merged prep: precompute A/C  +  weight f16 pieces ----------------
__global__ void __launch_bounds__(256) prep_all(
    const float* __restrict__ x_aux, const float* __restrict__ g1w, const float* __restrict__ g1b,
    const float* __restrict__ g2w, const float* __restrict__ g3w, const float* __restrict__ g4w)
{
    int blk = blockIdx.x;
    if (blk >= 256) {
        // ---- weight piece p = L*4 + kc : [n=256][k=64] f16, XOR swizzle ----
        int p = blk - 256;
        int L = p >> 2, kc = p & 3;
        const float* W = (L == 0) ? g2w : (L == 1) ? g3w : g4w;
        int n = threadIdx.x;
        unsigned char* dst = g_Wp + (size_t)p * 32768;
#pragma unroll 4
        for (int k2 = 0; k2 < 32; ++k2) {
            int k = 2 * k2, kg = kc * 64 + k;
            float w0 = W[kg * 256 + n], w1 = W[(kg + 1) * 256 + n];
            unsigned off = (unsigned)n * 128 + ((((unsigned)k >> 3) ^ ((unsigned)n & 7)) << 4)
                         + ((unsigned)k & 7) * 2;
            *(unsigned*)(dst + off) = cvt_h2(w1, w0);
        }
        return;
    }
    // ---- A/C precompute (g1 decomposition), 8 i's per block ----
    int b = blk >> 3, ig = blk & 7;
    int o = threadIdx.x;
    __shared__ float xs[8][128];
#pragma unroll
    for (int it = 0; it < 4; ++it) {
        int v = o + 256 * it, r = v >> 7, k = v & 127;
        xs[r][k] = x_aux[(size_t)(b * 64 + ig * 8 + r) * 128 + k];
    }
    __syncthreads();

    float w64 = g1w[64 * 256 + o], w193 = g1w[193 * 256 + o], bb = g1b[o];
    float accA[8], accC[8];
#pragma unroll
    for (int r = 0; r < 8; ++r) {
        float fi = (float)(ig * 8 + r);
        accA[r] = fi * w64;
        accC[r] = fmaf(fi, w193, bb);
    }
#pragma unroll 4
    for (int k = 0; k < 64; ++k) {
        float w = g1w[k * 256 + o];
#pragma unroll
        for (int r = 0; r < 8; ++r) accA[r] = fmaf(xs[r][k], w, accA[r]);
    }
#pragma unroll 4
    for (int k = 0; k < 128; ++k) {
        float w = g1w[(65 + k) * 256 + o];
#pragma unroll
        for (int r = 0; r < 8; ++r) accC[r] = fmaf(xs[r][k], w, accC[r]);
    }
#pragma unroll
    for (int r = 0; r < 8; ++r) {
        int biq = b * 64 + ig * 8 + r;
        g_A[biq * 256 + o] = accA[r];
        g_C[biq * 256 + o] = accC[r];
    }
    if (ig == 0) g_xg[b * 256 + o] = 0.f;
}

// ---------------- main: fused g2..g4 on mma.sync f16 + pooling ----------------
__global__ void __launch_bounds__(256, 1) main_kernel(
    const float* __restrict__ g2b, const float* __restrict__ g3b, const float* __restrict__ g4b)
{
    extern __shared__ char smem[];
    unsigned sb = s2u(smem);
    int tid = threadIdx.x, l = tid & 31, wid = tid >> 5;
    int wm = wid & 1, wn = wid >> 1;                    // 2(M) x 4(N) warp grid
    int bi = blockIdx.x;                                // 1024 CTAs
    int b = bi >> 5, i0 = (bi & 31) * 2;

    float* bias_s = (float*)(smem + BIAS_OFF);
    bias_s[tid] = g2b[tid];
    bias_s[256 + tid] = g3b[tid];
    bias_s[512 + tid] = g4b[tid];

    // prologue: async-load weight pieces 0 and 1 into slots 0,1
#pragma unroll
    for (int s = 0; s < 2; ++s) {
        const unsigned char* src = g_Wp + (size_t)s * 32768;
        unsigned dst = sb + W_OFF + s * 32768;
#pragma unroll
        for (int i = 0; i < 8; ++i) {
            int off = (tid + 256 * i) * 16;
            cpasync16(dst + off, src + off);
        }
        CP_COMMIT();
    }

    // ---- h1 fill: A chunks <- relu(gA[b,i] + gC[b,j]) as f16, swizzled ----
    {
        int cp = tid & 127, jh = tid >> 7;
        int c0 = 2 * cp;
        float2 av0 = *(const float2*)(g_A + (size_t)(b * 64 + i0) * 256 + c0);
        float2 av1 = *(const float2*)(g_A + (size_t)(b * 64 + i0 + 1) * 256 + c0);
        const float* Cb = g_C + (size_t)(b * 64) * 256;
        unsigned cbase = (unsigned)(c0 >> 6) * 16384;
        unsigned kcol = (unsigned)((c0 & 63) >> 3);
        unsigned kbyt = (unsigned)(c0 & 7) * 2;
#pragma unroll 2
        for (int jj = 0; jj < 32; ++jj) {
            int j = jh * 32 + jj;
            float2 cv = *(const float2*)(Cb + (size_t)j * 256 + c0);
#pragma unroll
            for (int ii = 0; ii < 2; ++ii) {
                int m = ii * 64 + j;
                float ax = ii ? av1.x : av0.x, ay = ii ? av1.y : av0.y;
                float v0 = fmaxf(ax + cv.x, 0.f);
                float v1 = fmaxf(ay + cv.y, 0.f);
                unsigned off = cbase + (unsigned)m * 128
                             + ((kcol ^ ((unsigned)m & 7)) << 4) + kbyt;
                *(unsigned*)(smem + off) = cvt_h2(v1, v0);
            }
        }
    }

    // lane-constant address components
    unsigned arow = (unsigned)(wm * 64 + (l & 15));
    unsigned abase = sb + arow * 128;           // A_OFF = 0
    unsigned asw = (unsigned)(l & 7);
    unsigned ahb = (unsigned)(l >> 4);
    // B ldsm_x4 lane mapping: row=(l&7), k-half=(l>>3)&1, nt-offset=(l>>4)
    unsigned bbase = sb + W_OFF + (unsigned)((wn * 64 + (l >> 4) * 8 + (l & 7)) * 128);
    unsigned bsw = (unsigned)(l & 7);
    unsigned bhb = (unsigned)((l >> 3) & 1);

    float acc[4][8][4];
    unsigned esw = (unsigned)(l >> 2);          // row&7 in epilogue
    int cl = l & 3;

#pragma unroll 1
    for (int t = 0; t < 12; ++t) {
        CP_WAIT1();
        __syncthreads();          // piece t visible to all; all warps finished step t-1
        int slot3 = t - (t / 3) * 3;
        int c = t & 3;

        if (c == 0) {
#pragma unroll
            for (int mt = 0; mt < 4; ++mt)
#pragma unroll
                for (int nt = 0; nt < 8; ++nt)
#pragma unroll
                    for (int e = 0; e < 4; ++e) acc[mt][nt][e] = 0.f;
        }

        unsigned acb = abase + (unsigned)c * 16384;
        unsigned bsl = bbase + (unsigned)slot3 * 32768;
#pragma unroll
        for (int ks = 0; ks < 4; ++ks) {
            unsigned a[4][4];
            unsigned kxa = (((unsigned)(ks * 2) + ahb) ^ asw) << 4;
#pragma unroll
            for (int mt = 0; mt < 4; ++mt)
                ldsm_x4(acb + mt * 2048 + kxa, a[mt][0], a[mt][1], a[mt][2], a[mt][3]);
            unsigned kxb = (((unsigned)(ks * 2) + bhb) ^ bsw) << 4;
#pragma unroll
            for (int np = 0; np < 4; ++np) {
                unsigned b0, b1, b2, b3;
                ldsm_x4(bsl + np * 2048 + kxb, b0, b1, b2, b3);
#pragma unroll
                for (int mt = 0; mt < 4; ++mt) {
                    mma_f16(acc[mt][2 * np], a[mt], b0, b1);
                    mma_f16(acc[mt][2 * np + 1], a[mt], b2, b3);
                }
            }
        }

        // prefetch piece t+2 into slot (t+2)%3 — safe: that slot was last read in
        // step t-1, and the top-of-step barrier proves every warp finished step t-1.
        if (t + 2 < 12) {
            int s2 = t + 2, slot_n = s2 - (s2 / 3) * 3;
            const unsigned char* src = g_Wp + (size_t)s2 * 32768;
            unsigned dst = sb + W_OFF + slot_n * 32768;
#pragma unroll
            for (int i = 0; i < 8; ++i) {
                int off = (tid + 256 * i) * 16;
                cpasync16(dst + off, src + off);
            }
        }
        CP_COMMIT();

        if (c == 3) {
            __syncthreads();      // all MMA reads of A done before rewrite
            int L = t >> 2;
            if (L < 2) {
                // bias+relu, write back as next layer's A (f16, swizzled)
                int r0 = wm * 64 + (l >> 2);
#pragma unroll
                for (int nt = 0; nt < 8; ++nt) {
                    float b0 = bias_s[L * 256 + wn * 64 + nt * 8 + 2 * cl];
                    float b1 = bias_s[L * 256 + wn * 64 + nt * 8 + 2 * cl + 1];
#pragma unroll
                    for (int mt = 0; mt < 4; ++mt) {
                        int ra = r0 + mt * 16, rb = ra + 8;
                        unsigned pa = cvt_h2(fmaxf(acc[mt][nt][1] + b1, 0.f),
                                             fmaxf(acc[mt][nt][0] + b0, 0.f));
                        unsigned pb = cvt_h2(fmaxf(acc[mt][nt][3] + b1, 0.f),
                                             fmaxf(acc[mt][nt][2] + b0, 0.f));
                        unsigned swc = ((unsigned)nt ^ esw) << 4;
                        *(unsigned*)(smem + wn * 16384 + ra * 128 + swc + 4 * cl) = pa;
                        *(unsigned*)(smem + wn * 16384 + rb * 128 + swc + 4 * cl) = pb;
                    }
                }
            } else {
                // g4: bias+relu, row-sum, atomic pool
#pragma unroll
                for (int nt = 0; nt < 8; ++nt) {
                    float b0 = bias_s[512 + wn * 64 + nt * 8 + 2 * cl];
                    float b1 = bias_s[512 + wn * 64 + nt * 8 + 2 * cl + 1];
                    float s0 = 0.f, s1 = 0.f;
#pragma unroll
                    for (int mt = 0; mt < 4; ++mt) {
                        s0 += fmaxf(acc[mt][nt][0] + b0, 0.f) + fmaxf(acc[mt][nt][2] + b0, 0.f);
                        s1 += fmaxf(acc[mt][nt][1] + b1, 0.f) + fmaxf(acc[mt][nt][3] + b1, 0.f);
                    }
                    s0 += __shfl_xor_sync(0xFFFFFFFFu, s0, 4);
                    s0 += __shfl_xor_sync(0xFFFFFFFFu, s0, 8);
                    s0 += __shfl_xor_sync(0xFFFFFFFFu, s0, 16);
                    s1 += __shfl_xor_sync(0xFFFFFFFFu, s1, 4);
                    s1 += __shfl_xor_sync(0xFFFFFFFFu, s1, 8);
                    s1 += __shfl_xor_sync(0xFFFFFFFFu, s1, 16);
                    if (l < 4) {
                        atomicAdd(&g_xg[b * 256 + wn * 64 + nt * 8 + 2 * l], s0);
                        atomicAdd(&g_xg[b * 256 + wn * 64 + nt * 8 + 2 * l + 1], s1);
                    }
                }
            }
            __syncthreads();
        }
    }
}

// ---------------- fused f-MLP: one launch, 32 CTAs x 1024 threads, 4-way k-split ----------------
__global__ void __launch_bounds__(1024) f_fused(
    const float* __restrict__ f1w, const float* __restrict__ f1b,
    const float* __restrict__ f2w, const float* __restrict__ f2b,
    const float* __restrict__ f3w, const float* __restrict__ f3b,
    float* __restrict__ out)
{
    int b = blockIdx.x;
    int tid = threadIdx.x;
    int o = tid & 255, kp = tid >> 8;          // 4 k-parts of 64
    __shared__ float xs[256];
    __shared__ float ys[256];
    __shared__ float red[4][256];

    if (tid < 256) xs[tid] = g_xg[b * 256 + tid];
    __syncthreads();

    // layer 1
    {
        float acc = 0.f;
#pragma unroll 8
        for (int kk = 0; kk < 64; ++kk) {
            int k = kp * 64 + kk;
            acc = fmaf(xs[k], f1w[k * 256 + o], acc);
        }
        red[kp][o] = acc;
        __syncthreads();
        if (tid < 256) {
            float s = red[0][tid] + red[1][tid] + red[2][tid] + red[3][tid] + f1b[tid];
            ys[tid] = fmaxf(s, 0.f);
        }
        __syncthreads();
    }
    // layer 2
    {
        float acc = 0.f;
#pragma unroll 8
        for (int kk = 0; kk < 64; ++kk) {
            int k = kp * 64 + kk;
            acc = fmaf(ys[k], f2w[k * 256 + o], acc);
        }
        red[kp][o] = acc;
        __syncthreads();
        if (tid < 256) {
            float s = red[0][tid] + red[1][tid] + red[2][tid] + red[3][tid] + f2b[tid];
            xs[tid] = fmaxf(s, 0.f);
        }
        __syncthreads();
    }
    // layer 3
    {
        float acc = 0.f;
#pragma unroll 8
        for (int kk = 0; kk < 64; ++kk) {
            int k = kp * 64 + kk;
            acc = fmaf(xs[k], f3w[k * 256 + o], acc);
        }
        red[kp][o] = acc;
        __syncthreads();
        if (tid < 256)
            out[b * 256 + tid] = red[0][tid] + red[1][tid] + red[2][tid] + red[3][tid] + f3b[tid];
    }
}

// ---------------- launch ----------------
extern "C" void kernel_launch(void* const* d_in, const int* in_sizes, int n_in,
                              void* d_out, int out_size)
{
    const float* x_aux = (const float*)d_in[0];
    const float* g1w   = (const float*)d_in[1];
    const float* g1b   = (const float*)d_in[2];
    const float* g2w   = (const float*)d_in[3];
    const float* g2b   = (const float*)d_in[4];
    const float* g3w   = (const float*)d_in[5];
    const float* g3b   = (const float*)d_in[6];
    const float* g4w   = (const float*)d_in[7];
    const float* g4b   = (const float*)d_in[8];
    const float* f1w   = (const float*)d_in[9];
    const float* f1b   = (const float*)d_in[10];
    const float* f2w   = (const float*)d_in[11];
    const float* f2b   = (const float*)d_in[12];
    const float* f3w   = (const float*)d_in[13];
    const float* f3b   = (const float*)d_in[14];
    float* out = (float*)d_out;

    cudaFuncSetAttribute(main_kernel, cudaFuncAttributeMaxDynamicSharedMemorySize, SMEM_SZ);

    prep_all<<<268, 256>>>(x_aux, g1w, g1b, g2w, g3w, g4w);
    main_kernel<<<1024, 256, SMEM_SZ>>>(g2b, g3b, g4b);
    f_fused<<<NB, 1024>>>(f1w, f1b, f2w, f2b, f3w, f3b, out);
}